// round 5
// baseline (speedup 1.0000x reference)
#include <cuda_runtime.h>
#include <cuda_bf16.h>
#include <cstdint>

// Problem constants (from reference):
//   radar_patches, mde_out_patches: (W, B, C, H, 1) float32, C = 1
//   output: (B, C, H, W) float32
#define PW 1600
#define PB 4
#define PH 900
#define NCOL (PW * PB)          // 6400 columns, each contiguous H floats
#define MDE_PAD 1024            // padded mde length (multiple of 128)

// 23 MB scratch for column results in (w,b,h) layout (coalesced writes),
// transposed into the (b,h,w) output by a second kernel.
__device__ float g_cols[(size_t)NCOL * PH];

__device__ __forceinline__ bool better(float v1, int i1, float v2, int i2) {
    // strictly smaller value wins; on exact fp32 tie, smaller index wins
    return (v1 < v2) || (v1 == v2 && (unsigned)i1 < (unsigned)i2);
}

__global__ __launch_bounds__(256) void radar_column_kernel(
    const float* __restrict__ radar,   // (W,B,H) contiguous per column
    const float* __restrict__ mde,     // (W,B,H)
    float* __restrict__ cols)          // (W,B,H) scratch
{
    __shared__ __align__(16) float s_mde[MDE_PAD];
    __shared__ float s_col[PH];
    __shared__ int   s_cnt[256];
    __shared__ int   s_entryY[PH];
    __shared__ float s_entryD[PH];
    __shared__ int   s_bestY[PH];
    __shared__ int   s_nvalid;

    const int colId = blockIdx.x;                 // w*B + b
    const float* rcol = radar + (size_t)colId * PH;
    const float* mcol = mde   + (size_t)colId * PH;
    const int tid  = threadIdx.x;
    const int lane = tid & 31;
    const int wid  = tid >> 5;

    const float NANF = __int_as_float(0x7fc00000);
    const float INFF = __int_as_float(0x7f800000);

    // ---- load mde into shared, NaN-ing invalid (==0) and padded entries ----
    // 256 float4 vectors cover [0,1024). Column base is 3600B -> 16B aligned.
    {
        float4 m;
        if (tid < PH / 4) {                       // tid < 225: fully in-bounds
            m = reinterpret_cast<const float4*>(mcol)[tid];
            m.x = (m.x != 0.0f) ? m.x : NANF;
            m.y = (m.y != 0.0f) ? m.y : NANF;
            m.z = (m.z != 0.0f) ? m.z : NANF;
            m.w = (m.w != 0.0f) ? m.w : NANF;
        } else {
            m = make_float4(NANF, NANF, NANF, NANF);
        }
        reinterpret_cast<float4*>(s_mde)[tid] = m;
    }
    // init occupancy column
    for (int i = tid; i < PH; i += 256) s_col[i] = 0.0f;

    // ---- ordered compaction of valid radar entries (ascending y) ----
    const int y0 = tid * 4;
    float v0 = 0.f, v1 = 0.f, v2 = 0.f, v3 = 0.f;
    if (tid < PH / 4) {                           // 4*tid+3 <= 899
        float4 r = reinterpret_cast<const float4*>(rcol)[tid];
        v0 = r.x; v1 = r.y; v2 = r.z; v3 = r.w;
    }
    int cnt = (v0 != 0.0f) + (v1 != 0.0f) + (v2 != 0.0f) + (v3 != 0.0f);
    s_cnt[tid] = cnt;
    __syncthreads();

    if (tid == 0) {
        int acc = 0;
        #pragma unroll 8
        for (int t = 0; t < 256; t++) { int c = s_cnt[t]; s_cnt[t] = acc; acc += c; }
        s_nvalid = acc;
    }
    __syncthreads();

    {
        int off = s_cnt[tid];
        if (v0 != 0.0f) { s_entryY[off] = y0 + 0; s_entryD[off] = v0; off++; }
        if (v1 != 0.0f) { s_entryY[off] = y0 + 1; s_entryD[off] = v1; off++; }
        if (v2 != 0.0f) { s_entryY[off] = y0 + 2; s_entryD[off] = v2; off++; }
        if (v3 != 0.0f) { s_entryY[off] = y0 + 3; s_entryD[off] = v3; off++; }
    }
    __syncthreads();
    const int nvalid = s_nvalid;

    // ---- warp-per-entry argmin |mde - d| with first-index tie-break ----
    for (int e = wid; e < nvalid; e += 8) {
        const float d = s_entryD[e];

        // 4 independent accumulator chains (one per float4 slot) for ILP.
        float mv0 = INFF, mv1 = INFF, mv2 = INFF, mv3 = INFF;
        int   mi0 = -1,   mi1 = -1,   mi2 = -1,   mi3 = -1;

        #pragma unroll
        for (int i = 0; i < MDE_PAD / 128; i++) {   // 8 iterations
            const int base = i * 128 + lane * 4;
            float4 m = reinterpret_cast<const float4*>(s_mde)[base >> 2];
            float d0 = fabsf(m.x - d);
            float d1 = fabsf(m.y - d);
            float d2 = fabsf(m.z - d);
            float d3 = fabsf(m.w - d);
            // NaN entries never satisfy strict < : padding / invalid excluded.
            if (d0 < mv0) { mv0 = d0; mi0 = base + 0; }
            if (d1 < mv1) { mv1 = d1; mi1 = base + 1; }
            if (d2 < mv2) { mv2 = d2; mi2 = base + 2; }
            if (d3 < mv3) { mv3 = d3; mi3 = base + 3; }
        }
        // merge the 4 chains (value, tie -> min index)
        float mv = mv0; int mi = mi0;
        if (better(mv1, mi1, mv, mi)) { mv = mv1; mi = mi1; }
        if (better(mv2, mi2, mv, mi)) { mv = mv2; mi = mi2; }
        if (better(mv3, mi3, mv, mi)) { mv = mv3; mi = mi3; }

        // warp reduction
        #pragma unroll
        for (int s = 16; s >= 1; s >>= 1) {
            float ov = __shfl_xor_sync(0xffffffffu, mv, s);
            int   oi = __shfl_xor_sync(0xffffffffu, mi, s);
            if (better(ov, oi, mv, mi)) { mv = ov; mi = oi; }
        }
        if (lane == 0)
            s_bestY[e] = (mi < 0) ? s_entryY[e] : mi;   // no valid mde -> y
    }
    __syncthreads();

    // ---- sequential placement (exact reference semantics) ----
    if (tid == 0) {
        for (int e = 0; e < nvalid; e++) {
            const int   by  = s_bestY[e];
            const float dep = s_entryD[e];
            if (s_col[by] == 0.0f) { s_col[by] = dep; continue; }
            int placed = -1;
            for (int dlt = 1; dlt < PH; dlt++) {
                int p = by + dlt;
                if (p < PH && s_col[p] == 0.0f) { placed = p; break; }
                p = by - dlt;
                if (p >= 0 && s_col[p] == 0.0f) { placed = p; break; }
            }
            s_col[placed < 0 ? by : placed] = dep;      // all full -> overwrite
        }
    }
    __syncthreads();

    // ---- coalesced write of the column to scratch ----
    float* outc = cols + (size_t)colId * PH;
    for (int i = tid; i < PH; i += 256) outc[i] = s_col[i];
}

// cols (W,B,H) -> out (B,1,H,W), tiled shared-memory transpose
__global__ __launch_bounds__(256) void radar_transpose_kernel(
    const float* __restrict__ cols, float* __restrict__ out)
{
    __shared__ float tile[32][33];
    const int b     = blockIdx.z;
    const int wBase = blockIdx.x * 32;
    const int hBase = blockIdx.y * 32;
    const int tx = threadIdx.x;        // 32
    const int ty = threadIdx.y;        // 8

    // read: consecutive tx -> consecutive h (contiguous in cols)
    #pragma unroll
    for (int j = 0; j < 32; j += 8) {
        const int w = wBase + ty + j;
        const int h = hBase + tx;
        float v = 0.0f;
        if (h < PH) v = cols[((size_t)w * PB + b) * PH + h];
        tile[ty + j][tx] = v;
    }
    __syncthreads();
    // write: consecutive tx -> consecutive w (contiguous in out)
    #pragma unroll
    for (int j = 0; j < 32; j += 8) {
        const int h = hBase + ty + j;
        const int w = wBase + tx;
        if (h < PH) out[((size_t)b * PH + h) * PW + w] = tile[tx][ty + j];
    }
}

extern "C" void kernel_launch(void* const* d_in, const int* in_sizes, int n_in,
                              void* d_out, int out_size)
{
    const float* radar = (const float*)d_in[0];   // radar_patches (W,B,1,H,1)
    const float* mde   = (const float*)d_in[1];   // mde_out_patches (W,B,1,H,1)
    float* out = (float*)d_out;                   // (B,1,H,W) float32

    float* cols;
    cudaGetSymbolAddress((void**)&cols, g_cols);

    radar_column_kernel<<<NCOL, 256>>>(radar, mde, cols);

    dim3 tgrid(PW / 32, (PH + 31) / 32, PB);      // 50 x 29 x 4
    dim3 tblk(32, 8);
    radar_transpose_kernel<<<tgrid, tblk>>>(cols, out);
}

// round 9
// speedup vs baseline: 1.9055x; 1.9055x over previous
#include <cuda_runtime.h>
#include <cuda_bf16.h>
#include <cstdint>

// Problem constants:
//   radar_patches, mde_out_patches: (W, B, C=1, H, 1) float32
//   output: (B, 1, H, W) float32
#define PW 1600
#define PB 4
#define PH 900
#define NCOL (PW * PB)              // 6400 columns, each contiguous H floats
#define NBUCK 128
#define BSCALE (128.0f / 82.0f)     // depths in [1,81]; clamped anyway
#define SAFE_R 0.6f                 // < bucket width 0.640625 -> exactness guaranteed

// 23 MB scratch for column results in (w,b,h) layout (coalesced writes),
// transposed into the (b,h,w) output by a second kernel.
__device__ float g_cols[(size_t)NCOL * PH];

__device__ __forceinline__ int bucket_of(float v) {
    int b = __float2int_rd(v * BSCALE);
    return min(NBUCK - 1, max(0, b));
}

__global__ __launch_bounds__(256) void radar_column_kernel(
    const float* __restrict__ radar,   // (W,B,H) contiguous per column
    const float* __restrict__ mde,     // (W,B,H)
    float* __restrict__ cols)          // (W,B,H) scratch
{
    // per-query running best: key = (|diff|_bits << 10) | mde_index  (lex min == argmin w/ first-index tie)
    __shared__ unsigned long long s_best[PH];
    __shared__ float          s_entryD[PH];
    __shared__ unsigned short s_entryY[PH];
    __shared__ unsigned short s_bestY[PH];
    __shared__ unsigned short s_qlist[PH];     // query ids grouped by depth bucket
    __shared__ unsigned short s_fb[PH];        // fallback query list (rare)
    __shared__ int   s_qstart[NBUCK + 1];
    __shared__ int   s_qcur[NBUCK];
    __shared__ __align__(16) float s_col[PH];
    __shared__ int   s_wsum[8];
    __shared__ int   s_nvalid, s_nmde, s_nfb;

    const int colId = blockIdx.x;              // w*B + b
    const float* rcol = radar + (size_t)colId * PH;
    const float* mcol = mde   + (size_t)colId * PH;
    const int tid  = threadIdx.x;
    const int lane = tid & 31;
    const int wid  = tid >> 5;

    // ---- init shared state ----
    for (int i = tid; i < PH; i += 256) { s_best[i] = ~0ull; s_col[i] = 0.0f; }
    if (tid < NBUCK) s_qcur[tid] = 0;
    if (tid == 0) { s_nfb = 0; s_nmde = 0; }

    // ---- load radar + mde (registers; column base 3600B -> 16B aligned) ----
    const int y0 = tid * 4;
    float r0 = 0.f, r1 = 0.f, r2 = 0.f, r3 = 0.f;
    float m0 = 0.f, m1 = 0.f, m2 = 0.f, m3 = 0.f;
    if (tid < PH / 4) {                        // tid < 225
        float4 r = reinterpret_cast<const float4*>(rcol)[tid];
        float4 m = reinterpret_cast<const float4*>(mcol)[tid];
        r0 = r.x; r1 = r.y; r2 = r.z; r3 = r.w;
        m0 = m.x; m1 = m.y; m2 = m.z; m3 = m.w;
    }
    const int cnt = (r0 != 0.f) + (r1 != 0.f) + (r2 != 0.f) + (r3 != 0.f);
    int mcnt      = (m0 != 0.f) + (m1 != 0.f) + (m2 != 0.f) + (m3 != 0.f);

    // warp inclusive scan of valid-radar counts
    int incl = cnt;
    #pragma unroll
    for (int s = 1; s < 32; s <<= 1) {
        int o = __shfl_up_sync(0xffffffffu, incl, s);
        if (lane >= s) incl += o;
    }
    if (lane == 31) s_wsum[wid] = incl;
    // warp reduce valid-mde count
    #pragma unroll
    for (int s = 16; s >= 1; s >>= 1) mcnt += __shfl_xor_sync(0xffffffffu, mcnt, s);

    __syncthreads();                                           // bar1: init + wsum done

    if (lane == 0) atomicAdd(&s_nmde, mcnt);
    if (tid == 0) {
        int acc = 0;
        #pragma unroll
        for (int w = 0; w < 8; w++) { int c = s_wsum[w]; s_wsum[w] = acc; acc += c; }
        s_nvalid = acc;
    }
    __syncthreads();                                           // bar2

    // ---- scatter valid radar entries (ascending y) + query bucket histogram ----
    {
        int off = s_wsum[wid] + incl - cnt;
        if (r0 != 0.f) { s_entryY[off] = (unsigned short)(y0 + 0); s_entryD[off] = r0; atomicAdd(&s_qcur[bucket_of(r0)], 1); off++; }
        if (r1 != 0.f) { s_entryY[off] = (unsigned short)(y0 + 1); s_entryD[off] = r1; atomicAdd(&s_qcur[bucket_of(r1)], 1); off++; }
        if (r2 != 0.f) { s_entryY[off] = (unsigned short)(y0 + 2); s_entryD[off] = r2; atomicAdd(&s_qcur[bucket_of(r2)], 1); off++; }
        if (r3 != 0.f) { s_entryY[off] = (unsigned short)(y0 + 3); s_entryD[off] = r3; atomicAdd(&s_qcur[bucket_of(r3)], 1); off++; }
    }
    __syncthreads();                                           // bar3

    // ---- warp0: exclusive scan of 128-bucket query histogram ----
    if (wid == 0) {
        const int b4 = lane * 4;
        int c0 = s_qcur[b4 + 0], c1 = s_qcur[b4 + 1], c2 = s_qcur[b4 + 2], c3 = s_qcur[b4 + 3];
        int tot = c0 + c1 + c2 + c3;
        int isum = tot;
        #pragma unroll
        for (int s = 1; s < 32; s <<= 1) {
            int o = __shfl_up_sync(0xffffffffu, isum, s);
            if (lane >= s) isum += o;
        }
        int ex = isum - tot;
        s_qstart[b4 + 0] = ex;
        s_qstart[b4 + 1] = ex + c0;
        s_qstart[b4 + 2] = ex + c0 + c1;
        s_qstart[b4 + 3] = ex + c0 + c1 + c2;
        s_qcur[b4 + 0] = ex;                 // reset as scatter cursors
        s_qcur[b4 + 1] = ex + c0;
        s_qcur[b4 + 2] = ex + c0 + c1;
        s_qcur[b4 + 3] = ex + c0 + c1 + c2;
        if (lane == 31) s_qstart[NBUCK] = isum;
    }
    __syncthreads();                                           // bar4
    const int nvalid = s_nvalid;

    // ---- scatter query ids into bucket-grouped list ----
    for (int e = tid; e < nvalid; e += 256) {
        int b = bucket_of(s_entryD[e]);
        int pos = atomicAdd(&s_qcur[b], 1);
        s_qlist[pos] = (unsigned short)e;
    }
    __syncthreads();                                           // bar5

    // ---- main pass: each mde element updates queries within +-2 depth buckets ----
    if (nvalid > 0) {
        float mv[4] = {m0, m1, m2, m3};
        #pragma unroll
        for (int k = 0; k < 4; k++) {
            float v = mv[k];
            if (v == 0.0f) continue;                           // invalid mde excluded
            int b  = bucket_of(v);
            int lo = max(0, b - 2), hi = min(NBUCK - 1, b + 2);
            int js = s_qstart[lo], je = s_qstart[hi + 1];
            for (int j = js; j < je; j++) {
                int q = s_qlist[j];
                float diff = fabsf(v - s_entryD[q]);
                unsigned long long key =
                    ((unsigned long long)__float_as_uint(diff) << 10) | (unsigned)(y0 + k);
                if (key < s_best[q]) atomicMin(&s_best[q], key);
            }
        }
    }
    __syncthreads();                                           // bar6

    // ---- resolve bestY; collect rare fallbacks ----
    const int nmde = s_nmde;
    for (int e = tid; e < nvalid; e += 256) {
        if (nmde == 0) { s_bestY[e] = s_entryY[e]; continue; } // no valid mde -> own y
        unsigned long long k = s_best[e];
        if (k == ~0ull) { int p = atomicAdd(&s_nfb, 1); s_fb[p] = (unsigned short)e; continue; }
        float diff = __uint_as_float((unsigned)(k >> 10));
        if (diff > SAFE_R) { int p = atomicAdd(&s_nfb, 1); s_fb[p] = (unsigned short)e; }
        else               s_bestY[e] = (unsigned short)(k & 1023u);
    }
    __syncthreads();                                           // bar7

    // ---- fallback: exact brute-force argmin (warp per query; essentially never taken) ----
    {
        const int nfb = s_nfb;
        for (int f = wid; f < nfb; f += 8) {
            const int e = s_fb[f];
            const float d = s_entryD[e];
            unsigned long long bk = ~0ull;
            for (int i = lane; i < PH; i += 32) {
                float v = __ldg(&mcol[i]);
                if (v != 0.0f) {
                    float diff = fabsf(v - d);
                    unsigned long long key =
                        ((unsigned long long)__float_as_uint(diff) << 10) | (unsigned)i;
                    if (key < bk) bk = key;
                }
            }
            #pragma unroll
            for (int s = 16; s >= 1; s >>= 1) {
                unsigned long long o = __shfl_xor_sync(0xffffffffu, bk, s);
                if (o < bk) bk = o;
            }
            if (lane == 0)
                s_bestY[e] = (bk == ~0ull) ? s_entryY[e] : (unsigned short)(bk & 1023u);
        }
    }
    __syncthreads();                                           // bar8

    // ---- sequential placement (exact reference semantics) ----
    if (tid == 0) {
        for (int e = 0; e < nvalid; e++) {
            const int   by  = s_bestY[e];
            const float dep = s_entryD[e];
            if (s_col[by] == 0.0f) { s_col[by] = dep; continue; }
            int placed = -1;
            for (int dlt = 1; dlt < PH; dlt++) {
                int p = by + dlt;
                if (p < PH && s_col[p] == 0.0f) { placed = p; break; }
                p = by - dlt;
                if (p >= 0 && s_col[p] == 0.0f) { placed = p; break; }
            }
            s_col[placed < 0 ? by : placed] = dep;             // all full -> overwrite
        }
    }
    __syncthreads();                                           // bar9

    // ---- coalesced vectorized write of the column to scratch ----
    if (tid < PH / 4)
        reinterpret_cast<float4*>(cols + (size_t)colId * PH)[tid] =
            reinterpret_cast<const float4*>(s_col)[tid];
}

// cols (W,B,H) -> out (B,1,H,W), tiled shared-memory transpose
__global__ __launch_bounds__(256) void radar_transpose_kernel(
    const float* __restrict__ cols, float* __restrict__ out)
{
    __shared__ float tile[32][33];
    const int b     = blockIdx.z;
    const int wBase = blockIdx.x * 32;
    const int hBase = blockIdx.y * 32;
    const int tx = threadIdx.x;        // 32
    const int ty = threadIdx.y;        // 8

    #pragma unroll
    for (int j = 0; j < 32; j += 8) {
        const int w = wBase + ty + j;
        const int h = hBase + tx;
        float v = 0.0f;
        if (h < PH) v = cols[((size_t)w * PB + b) * PH + h];
        tile[ty + j][tx] = v;
    }
    __syncthreads();
    #pragma unroll
    for (int j = 0; j < 32; j += 8) {
        const int h = hBase + ty + j;
        const int w = wBase + tx;
        if (h < PH) out[((size_t)b * PH + h) * PW + w] = tile[tx][ty + j];
    }
}

extern "C" void kernel_launch(void* const* d_in, const int* in_sizes, int n_in,
                              void* d_out, int out_size)
{
    const float* radar = (const float*)d_in[0];   // radar_patches (W,B,1,H,1)
    const float* mde   = (const float*)d_in[1];   // mde_out_patches (W,B,1,H,1)
    float* out = (float*)d_out;                   // (B,1,H,W) float32

    float* cols;
    cudaGetSymbolAddress((void**)&cols, g_cols);

    radar_column_kernel<<<NCOL, 256>>>(radar, mde, cols);

    dim3 tgrid(PW / 32, (PH + 31) / 32, PB);      // 50 x 29 x 4
    dim3 tblk(32, 8);
    radar_transpose_kernel<<<tgrid, tblk>>>(cols, out);
}